// round 10
// baseline (speedup 1.0000x reference)
#include <cuda_runtime.h>
#include <cuda_bf16.h>
#include <cstdint>
#include <math.h>

#define B_   64
#define S_   512
#define E_   256
#define H_   512
#define O_   1000
#define NCTA 64
#define THR  256

// ---------------- device scratch ----------------
__device__ __nv_bfloat16 g_hA[2 * B_ * 1024];     // [buf][b][k]  k: hi[0,512) lo[512,1024)
__device__ __nv_bfloat16 g_embS[(size_t)S_ * B_ * 512]; // [s][b][k] k: hi[0,256) lo[256,512)
__device__ float g_xpre[(size_t)S_ * B_ * 2048];  // [s][b][col], col=j*4+g, bias folded
__device__ int   g_flag[NCTA * 32];

// ---------------- helpers ----------------
__device__ __forceinline__ int ld_acquire_gpu(const int* p) {
    int v; asm volatile("ld.acquire.gpu.global.s32 %0, [%1];" : "=r"(v) : "l"(p) : "memory");
    return v;
}
__device__ __forceinline__ void st_release_gpu(int* p, int v) {
    asm volatile("st.release.gpu.global.s32 [%0], %1;" :: "l"(p), "r"(v) : "memory");
}
__device__ __forceinline__ float sigf(float v) { return __fdividef(1.f, 1.f + __expf(-v)); }
__device__ __forceinline__ float tanhf_fast(float v) { return __fdividef(2.f, 1.f + __expf(-2.f * v)) - 1.f; }
__device__ __forceinline__ unsigned short bfhi(float w) {
    __nv_bfloat16 h = __float2bfloat16(w); unsigned short u; memcpy(&u, &h, 2); return u;
}
__device__ __forceinline__ unsigned short bflo(float w) {
    __nv_bfloat16 h = __float2bfloat16(w);
    __nv_bfloat16 l = __float2bfloat16(w - __bfloat162float(h));
    unsigned short u; memcpy(&u, &l, 2); return u;
}
__device__ __forceinline__ uint32_t smem_u32(const void* p) {
    uint32_t a;
    asm("{ .reg .u64 t; cvta.to.shared.u64 t, %1; cvt.u32.u64 %0, t; }" : "=r"(a) : "l"(p));
    return a;
}
#define LDSM4(r, addr) \
    asm volatile("ldmatrix.sync.aligned.m8n8.x4.shared.b16 {%0,%1,%2,%3}, [%4];" \
        : "=r"((r)[0]), "=r"((r)[1]), "=r"((r)[2]), "=r"((r)[3]) : "r"(addr))
#define MMA16816(d, a, bb) \
    asm volatile("mma.sync.aligned.m16n8k16.row.col.f32.bf16.bf16.f32 " \
        "{%0,%1,%2,%3},{%4,%5,%6,%7},{%8,%9},{%0,%1,%2,%3};" \
        : "+f"((d)[0]), "+f"((d)[1]), "+f"((d)[2]), "+f"((d)[3]) \
        : "r"((a)[0]), "r"((a)[1]), "r"((a)[2]), "r"((a)[3]), "r"((bb)[0]), "r"((bb)[1]))

__global__ void init_flags_kernel() { g_flag[threadIdx.x * 32] = 1; }

// ---------------- prep: h_0 split ----------------
__global__ void __launch_bounds__(256) a0_prep_kernel(const float* __restrict__ hidden_in) {
    int i = blockIdx.x * 256 + threadIdx.x;
    if (i >= B_ * H_) return;
    int b = i >> 9, j = i & 511;
    float h = hidden_in[b * H_ + j];
    unsigned short hi = bfhi(h), lo = bflo(h);
    memcpy(&g_hA[b * 1024 + j], &hi, 2);
    memcpy(&g_hA[b * 1024 + 512 + j], &lo, 2);
}

// ---------------- prep: embedding gather + split ----------------
__global__ void __launch_bounds__(256) embs_prep_kernel(
    const int* __restrict__ x, const float* __restrict__ embed_w) {
    const int s = blockIdx.x, t = threadIdx.x;
    const int b = t >> 2, eq = t & 3;
    const int row = x[b * S_ + s];
    const float* src = embed_w + (size_t)row * E_ + eq * 64;
    __nv_bfloat16* dst = g_embS + ((size_t)s * B_ + b) * 512;
#pragma unroll 8
    for (int e = 0; e < 64; ++e) {
        float w = src[e];
        unsigned short hi = bfhi(w), lo = bflo(w);
        memcpy(&dst[eq * 64 + e], &hi, 2);
        memcpy(&dst[256 + eq * 64 + e], &lo, 2);
    }
}

// ---------------- input GEMM via mma.sync ----------------
// K' map: [0,256) ehi*Whi ; [256,512) elo*Whi ; [512,768) ehi*Wlo.  A smem col = k'&511.
// grid (64 nt, 32 sg): CTA = cols [nt*32,+32), 16 steps. warp = K-slab of 96 (6 kt).
#define XROWB 1040
#define XSCR  66560
__global__ void __launch_bounds__(THR, 1) xpre_mma_kernel(
    const float* __restrict__ Wf, const float* __restrict__ Wi,
    const float* __restrict__ Wc, const float* __restrict__ Wo,
    const float* __restrict__ bf, const float* __restrict__ bi,
    const float* __restrict__ bc, const float* __restrict__ bo)
{
    extern __shared__ char sm[];
    float* scr = (float*)(sm + XSCR);          // [64][264] padded

    const int tid = threadIdx.x, wid = tid >> 5, lane = tid & 31;
    const int nt = blockIdx.x, sg = blockIdx.y;
    const float* W4[4] = {Wf, Wi, Wc, Wo};
    const float* Bi4[4] = {bf, bi, bc, bo};

    uint32_t Bf[6][4][2];
#pragma unroll
    for (int kt = 0; kt < 6; ++kt)
#pragma unroll
        for (int nf = 0; nf < 4; ++nf) {
            int n = nf * 8 + (lane >> 2);
            int j = nt * 8 + (n >> 2);
            const float* Wg = W4[n & 3];
#pragma unroll
            for (int p = 0; p < 2; ++p) {
                int k1 = wid * 96 + kt * 16 + (lane & 3) * 2 + p * 8;
                int k2 = k1 + 1;
                float w1 = Wg[(size_t)(H_ + (k1 & 255)) * H_ + j];
                float w2 = Wg[(size_t)(H_ + (k2 & 255)) * H_ + j];
                unsigned short v1 = (k1 >= 512) ? bflo(w1) : bfhi(w1);
                unsigned short v2 = (k2 >= 512) ? bflo(w2) : bfhi(w2);
                Bf[kt][nf][p] = (uint32_t)v1 | ((uint32_t)v2 << 16);
            }
        }

    const int b = tid >> 2, up = tid & 3;
    float bq[8];
#pragma unroll
    for (int q = 0; q < 8; ++q) bq[q] = Bi4[q & 3][nt * 8 + up * 2 + (q >> 2)];

    const uint32_t smA = smem_u32(sm);
    const uint32_t lm_base = smA + (lane & 15) * XROWB + (lane >> 4) * 16;

    for (int si = 0; si < 16; ++si) {
        const int s = sg * 16 + si;
        {   // stage A: 256B/thread
            const char* gsrc = (const char*)(g_embS + ((size_t)s * B_ + b) * 512) + up * 256;
            char* sdst = sm + b * XROWB + up * 256;
            for (int c = 0; c < 16; c += 4) {
                uint4 v0 = __ldcg((const uint4*)(gsrc + (c + 0) * 16));
                uint4 v1 = __ldcg((const uint4*)(gsrc + (c + 1) * 16));
                uint4 v2 = __ldcg((const uint4*)(gsrc + (c + 2) * 16));
                uint4 v3 = __ldcg((const uint4*)(gsrc + (c + 3) * 16));
                *(uint4*)(sdst + (c + 0) * 16) = v0;
                *(uint4*)(sdst + (c + 1) * 16) = v1;
                *(uint4*)(sdst + (c + 2) * 16) = v2;
                *(uint4*)(sdst + (c + 3) * 16) = v3;
            }
        }
        __syncthreads();

        // M split into two halves to cap accumulator registers
#pragma unroll
        for (int mh = 0; mh < 2; ++mh) {
            float acc[4][2][4];
#pragma unroll
            for (int nf = 0; nf < 4; ++nf)
#pragma unroll
                for (int m2 = 0; m2 < 2; ++m2) {
                    acc[nf][m2][0] = 0.f; acc[nf][m2][1] = 0.f;
                    acc[nf][m2][2] = 0.f; acc[nf][m2][3] = 0.f;
                }
#pragma unroll
            for (int kt = 0; kt < 6; ++kt) {
                uint32_t colB = (uint32_t)(((wid * 96 + kt * 16) & 511) * 2);
                uint32_t a[2][4];
#pragma unroll
                for (int m2 = 0; m2 < 2; ++m2)
                    LDSM4(a[m2], lm_base + (mh * 2 + m2) * 16 * XROWB + colB);
#pragma unroll
                for (int m2 = 0; m2 < 2; ++m2)
#pragma unroll
                    for (int nf = 0; nf < 4; ++nf)
                        MMA16816(acc[nf][m2], a[m2], Bf[kt][nf]);
            }
#pragma unroll
            for (int nf = 0; nf < 4; ++nf)
#pragma unroll
                for (int m2 = 0; m2 < 2; ++m2) {
                    int m = (mh * 2 + m2) * 16 + (lane >> 2);
                    int nn = nf * 8 + (lane & 3) * 2;
                    scr[m * 264 + wid * 32 + nn]           = acc[nf][m2][0];
                    scr[m * 264 + wid * 32 + nn + 1]       = acc[nf][m2][1];
                    scr[(m + 8) * 264 + wid * 32 + nn]     = acc[nf][m2][2];
                    scr[(m + 8) * 264 + wid * 32 + nn + 1] = acc[nf][m2][3];
                }
        }
        __syncthreads();

        float o[8];
#pragma unroll
        for (int q = 0; q < 8; ++q) {
            float ss = bq[q];
#pragma unroll
            for (int w8 = 0; w8 < 8; ++w8) ss += scr[b * 264 + w8 * 32 + up * 8 + q];
            o[q] = ss;
        }
        float* outp = g_xpre + ((size_t)s * B_ + b) * 2048 + nt * 32 + up * 8;
        *(float4*)(outp)     = make_float4(o[0], o[1], o[2], o[3]);
        *(float4*)(outp + 4) = make_float4(o[4], o[5], o[6], o[7]);
        __syncthreads();
    }
}

// ---------------- persistent recurrent LSTM via mma.sync ----------------
// K' map: [0,512) hhi*Whi ; [512,1024) hlo*Whi ; [1024,1536) hhi*Wlo. A col = k'&1023.
// 64 CTAs x 8 warps; warp = K-slab of 192 (12 kt), B-frags resident in regs.
#define RROWB 2064
#define RSCR  132096      // 64*2064
#define RSM   199680      // + 64*264*4
__global__ void __launch_bounds__(THR, 1) lstm_mma_kernel(
    const float* __restrict__ c_in,
    const float* __restrict__ Wf, const float* __restrict__ Wi,
    const float* __restrict__ Wc, const float* __restrict__ Wo,
    float* __restrict__ d_out)
{
    extern __shared__ char sm[];
    float* scr = (float*)(sm + RSCR);

    const int tid = threadIdx.x, wid = tid >> 5, lane = tid & 31;
    const int j0 = blockIdx.x * 8;
    const float* W4[4] = {Wf, Wi, Wc, Wo};

    uint32_t Bf[12][4][2];
#pragma unroll
    for (int kt = 0; kt < 12; ++kt)
#pragma unroll
        for (int nf = 0; nf < 4; ++nf) {
            int n = nf * 8 + (lane >> 2);
            int j = j0 + (n >> 2);
            const float* Wg = W4[n & 3];
#pragma unroll
            for (int p = 0; p < 2; ++p) {
                int k1 = wid * 192 + kt * 16 + (lane & 3) * 2 + p * 8;
                int k2 = k1 + 1;
                float w1 = Wg[(size_t)(k1 & 511) * H_ + j];
                float w2 = Wg[(size_t)(k2 & 511) * H_ + j];
                unsigned short v1 = (k1 >= 1024) ? bflo(w1) : bfhi(w1);
                unsigned short v2 = (k2 >= 1024) ? bflo(w2) : bfhi(w2);
                Bf[kt][nf][p] = (uint32_t)v1 | ((uint32_t)v2 << 16);
            }
        }

    const int b = tid >> 2, grp = tid & 3;
    float c0 = c_in[b * H_ + j0 + grp * 2 + 0];
    float c1 = c_in[b * H_ + j0 + grp * 2 + 1];

    const uint32_t smA = smem_u32(sm);
    const uint32_t lm_base = smA + (lane & 15) * RROWB + (lane >> 4) * 16;

    for (int s = 0; s < S_; ++s) {
        const int rbuf = s & 1;
        // flag barrier (R5 protocol)
        if (tid < NCTA) {
            const int* fl = &g_flag[tid * 32];
            while (ld_acquire_gpu(fl) < s + 1) { }
        }
        __syncthreads();
        {   // stage split h: 512B/thread
            const char* gsrc = (const char*)(g_hA + rbuf * (B_ * 1024) + b * 1024) + grp * 512;
            char* sdst = sm + b * RROWB + grp * 512;
            for (int c = 0; c < 32; c += 4) {
                uint4 v0 = __ldcg((const uint4*)(gsrc + (c + 0) * 16));
                uint4 v1 = __ldcg((const uint4*)(gsrc + (c + 1) * 16));
                uint4 v2 = __ldcg((const uint4*)(gsrc + (c + 2) * 16));
                uint4 v3 = __ldcg((const uint4*)(gsrc + (c + 3) * 16));
                *(uint4*)(sdst + (c + 0) * 16) = v0;
                *(uint4*)(sdst + (c + 1) * 16) = v1;
                *(uint4*)(sdst + (c + 2) * 16) = v2;
                *(uint4*)(sdst + (c + 3) * 16) = v3;
            }
        }
        __syncthreads();

        // M split into two halves to cap accumulator registers (no spill)
#pragma unroll
        for (int mh = 0; mh < 2; ++mh) {
            float acc[4][2][4];
#pragma unroll
            for (int nf = 0; nf < 4; ++nf)
#pragma unroll
                for (int m2 = 0; m2 < 2; ++m2) {
                    acc[nf][m2][0] = 0.f; acc[nf][m2][1] = 0.f;
                    acc[nf][m2][2] = 0.f; acc[nf][m2][3] = 0.f;
                }
#pragma unroll
            for (int kt = 0; kt < 12; ++kt) {
                uint32_t colB = (uint32_t)(((wid * 192 + kt * 16) & 1023) * 2);
                uint32_t a[2][4];
#pragma unroll
                for (int m2 = 0; m2 < 2; ++m2)
                    LDSM4(a[m2], lm_base + (mh * 2 + m2) * 16 * RROWB + colB);
#pragma unroll
                for (int m2 = 0; m2 < 2; ++m2)
#pragma unroll
                    for (int nf = 0; nf < 4; ++nf)
                        MMA16816(acc[nf][m2], a[m2], Bf[kt][nf]);
            }
#pragma unroll
            for (int nf = 0; nf < 4; ++nf)
#pragma unroll
                for (int m2 = 0; m2 < 2; ++m2) {
                    int m = (mh * 2 + m2) * 16 + (lane >> 2);
                    int nn = nf * 8 + (lane & 3) * 2;
                    scr[m * 264 + wid * 32 + nn]           = acc[nf][m2][0];
                    scr[m * 264 + wid * 32 + nn + 1]       = acc[nf][m2][1];
                    scr[(m + 8) * 264 + wid * 32 + nn]     = acc[nf][m2][2];
                    scr[(m + 8) * 264 + wid * 32 + nn + 1] = acc[nf][m2][3];
                }
        }
        __syncthreads();

        // reduce + xpre + gates; thread -> (batch b, units j0+grp*2, +1)
        float pa[8];
        {
            const float* xb = g_xpre + ((size_t)s * B_ + b) * 2048 + blockIdx.x * 32 + grp * 8;
            float4 xv0 = *(const float4*)xb;
            float4 xv1 = *(const float4*)(xb + 4);
            pa[0] = xv0.x; pa[1] = xv0.y; pa[2] = xv0.z; pa[3] = xv0.w;
            pa[4] = xv1.x; pa[5] = xv1.y; pa[6] = xv1.z; pa[7] = xv1.w;
        }
#pragma unroll
        for (int q = 0; q < 8; ++q) {
            float ss = 0.f;
#pragma unroll
            for (int w8 = 0; w8 < 8; ++w8) ss += scr[b * 264 + w8 * 32 + grp * 8 + q];
            pa[q] += ss;
        }
        float fg0 = sigf(pa[0]), ig0 = sigf(pa[1]), gg0 = tanhf_fast(pa[2]), og0 = sigf(pa[3]);
        c0 = fg0 * c0 + ig0 * gg0;
        float h0 = og0 * tanhf_fast(c0);
        float fg1 = sigf(pa[4]), ig1 = sigf(pa[5]), gg1 = tanhf_fast(pa[6]), og1 = sigf(pa[7]);
        c1 = fg1 * c1 + ig1 * gg1;
        float h1 = og1 * tanhf_fast(c1);

        if (s < S_ - 1) {
            const int wb = rbuf ^ 1;
            uint32_t hip = (uint32_t)bfhi(h0) | ((uint32_t)bfhi(h1) << 16);
            uint32_t lop = (uint32_t)bflo(h0) | ((uint32_t)bflo(h1) << 16);
            __nv_bfloat16* dst = g_hA + wb * (B_ * 1024) + b * 1024;
            *(uint32_t*)&dst[j0 + grp * 2]       = hip;
            *(uint32_t*)&dst[512 + j0 + grp * 2] = lop;
            __threadfence();
            __syncthreads();
            if (tid == 0) st_release_gpu(&g_flag[blockIdx.x * 32], s + 2);
        } else {
            d_out[B_ * O_ + b * H_ + j0 + grp * 2 + 0] = h0;
            d_out[B_ * O_ + b * H_ + j0 + grp * 2 + 1] = h1;
        }
    }
}

// ---------------- dense head ----------------
__global__ void __launch_bounds__(256) dense_out_kernel(
    const float* __restrict__ Wd, const float* __restrict__ bd,
    float* __restrict__ d_out)
{
    const int o  = blockIdx.x * 256 + threadIdx.x;
    const int b0 = blockIdx.y * 2;
    __shared__ float sh[2][H_];
    const float* hsrc = d_out + B_ * O_;
    for (int idx = threadIdx.x; idx < 2 * H_; idx += 256) {
        int bi = idx >> 9, j = idx & (H_ - 1);
        sh[bi][j] = hsrc[(b0 + bi) * H_ + j];
    }
    __syncthreads();
    if (o < O_) {
        float bias = bd[o];
        float acc0 = bias, acc1 = bias;
#pragma unroll 8
        for (int j = 0; j < H_; ++j) {
            float wv = Wd[(size_t)j * O_ + o];
            acc0 += sh[0][j] * wv;
            acc1 += sh[1][j] * wv;
        }
        d_out[(b0 + 0) * O_ + o] = acc0;
        d_out[(b0 + 1) * O_ + o] = acc1;
    }
}

// ---------------- launch ----------------
extern "C" void kernel_launch(void* const* d_in, const int* in_sizes, int n_in,
                              void* d_out, int out_size) {
    const int*   x        = (const int*)  d_in[0];
    const float* hidden   = (const float*)d_in[1];
    const float* c        = (const float*)d_in[2];
    const float* embed_w  = (const float*)d_in[3];
    const float* W_f      = (const float*)d_in[4];
    const float* b_f      = (const float*)d_in[5];
    const float* W_i      = (const float*)d_in[6];
    const float* b_i      = (const float*)d_in[7];
    const float* W_c      = (const float*)d_in[8];
    const float* b_c      = (const float*)d_in[9];
    const float* W_o      = (const float*)d_in[10];
    const float* b_o      = (const float*)d_in[11];
    const float* W_d      = (const float*)d_in[12];
    const float* b_d      = (const float*)d_in[13];
    float* out = (float*)d_out;

    static bool attr_set = false;
    if (!attr_set) {
        cudaFuncSetAttribute(xpre_mma_kernel,
                             cudaFuncAttributeMaxDynamicSharedMemorySize, XSCR + 67584);
        cudaFuncSetAttribute(lstm_mma_kernel,
                             cudaFuncAttributeMaxDynamicSharedMemorySize, RSM);
        attr_set = true;
    }

    init_flags_kernel<<<1, NCTA>>>();
    a0_prep_kernel<<<(B_ * H_ + 255) / 256, 256>>>(hidden);
    embs_prep_kernel<<<S_, 256>>>(x, embed_w);

    dim3 gx(64, 32);
    xpre_mma_kernel<<<gx, THR, XSCR + 67584>>>(W_f, W_i, W_c, W_o, b_f, b_i, b_c, b_o);

    lstm_mma_kernel<<<NCTA, THR, RSM>>>(c, W_f, W_i, W_c, W_o, out);

    dim3 g3(4, 32);
    dense_out_kernel<<<g3, 256>>>(W_d, b_d, out);
}

// round 12
// speedup vs baseline: 1.1823x; 1.1823x over previous
#include <cuda_runtime.h>
#include <cuda_bf16.h>
#include <cstdint>
#include <math.h>

#define B_   64
#define S_   512
#define E_   256
#define H_   512
#define O_   1000
#define NCTA 128          // persistent CTAs (4 units each)
#define THR  256

// ---------------- device scratch ----------------
__device__ __nv_bfloat16 g_hA[2 * B_ * 1024];     // [buf][b][k]  k: hi[0,512) lo[512,1024)
__device__ __nv_bfloat16 g_embS[(size_t)S_ * B_ * 512]; // [s][b][k] k: hi[0,256) lo[256,512)
__device__ float g_xpre[(size_t)S_ * B_ * 2048];  // [s][b][col], col=j*4+g, bias folded
__device__ int   g_flag[NCTA * 32];

// ---------------- helpers ----------------
__device__ __forceinline__ int ld_acquire_gpu(const int* p) {
    int v; asm volatile("ld.acquire.gpu.global.s32 %0, [%1];" : "=r"(v) : "l"(p) : "memory");
    return v;
}
__device__ __forceinline__ void st_release_gpu(int* p, int v) {
    asm volatile("st.release.gpu.global.s32 [%0], %1;" :: "l"(p), "r"(v) : "memory");
}
__device__ __forceinline__ float sigf(float v) { return __fdividef(1.f, 1.f + __expf(-v)); }
__device__ __forceinline__ float tanhf_fast(float v) { return __fdividef(2.f, 1.f + __expf(-2.f * v)) - 1.f; }
__device__ __forceinline__ unsigned short bfhi(float w) {
    __nv_bfloat16 h = __float2bfloat16(w); unsigned short u; memcpy(&u, &h, 2); return u;
}
__device__ __forceinline__ unsigned short bflo(float w) {
    __nv_bfloat16 h = __float2bfloat16(w);
    __nv_bfloat16 l = __float2bfloat16(w - __bfloat162float(h));
    unsigned short u; memcpy(&u, &l, 2); return u;
}
__device__ __forceinline__ uint32_t smem_u32(const void* p) {
    uint32_t a;
    asm("{ .reg .u64 t; cvta.to.shared.u64 t, %1; cvt.u32.u64 %0, t; }" : "=r"(a) : "l"(p));
    return a;
}
#define LDSM4(r, addr) \
    asm volatile("ldmatrix.sync.aligned.m8n8.x4.shared.b16 {%0,%1,%2,%3}, [%4];" \
        : "=r"((r)[0]), "=r"((r)[1]), "=r"((r)[2]), "=r"((r)[3]) : "r"(addr))
#define MMA16816(d, a, bb) \
    asm volatile("mma.sync.aligned.m16n8k16.row.col.f32.bf16.bf16.f32 " \
        "{%0,%1,%2,%3},{%4,%5,%6,%7},{%8,%9},{%0,%1,%2,%3};" \
        : "+f"((d)[0]), "+f"((d)[1]), "+f"((d)[2]), "+f"((d)[3]) \
        : "r"((a)[0]), "r"((a)[1]), "r"((a)[2]), "r"((a)[3]), "r"((bb)[0]), "r"((bb)[1]))
#define CP_ASYNC16(dst, src) \
    asm volatile("cp.async.cg.shared.global [%0], [%1], 16;" :: "r"(dst), "l"(src) : "memory")
#define CP_COMMIT() asm volatile("cp.async.commit_group;" ::: "memory")
#define CP_WAIT(n)  asm volatile("cp.async.wait_group %0;" :: "n"(n) : "memory")

__global__ void init_flags_kernel() { g_flag[threadIdx.x * 32] = 1; }

// ---------------- prep: h_0 split ----------------
__global__ void __launch_bounds__(256) a0_prep_kernel(const float* __restrict__ hidden_in) {
    int i = blockIdx.x * 256 + threadIdx.x;
    if (i >= B_ * H_) return;
    int b = i >> 9, j = i & 511;
    float h = hidden_in[b * H_ + j];
    unsigned short hi = bfhi(h), lo = bflo(h);
    memcpy(&g_hA[b * 1024 + j], &hi, 2);
    memcpy(&g_hA[b * 1024 + 512 + j], &lo, 2);
}

// ---------------- prep: embedding gather + split ----------------
__global__ void __launch_bounds__(256) embs_prep_kernel(
    const int* __restrict__ x, const float* __restrict__ embed_w) {
    const int s = blockIdx.x, t = threadIdx.x;
    const int b = t >> 2, eq = t & 3;
    const int row = x[b * S_ + s];
    const float* src = embed_w + (size_t)row * E_ + eq * 64;
    __nv_bfloat16* dst = g_embS + ((size_t)s * B_ + b) * 512;
#pragma unroll 8
    for (int e = 0; e < 64; ++e) {
        float w = src[e];
        unsigned short hi = bfhi(w), lo = bflo(w);
        memcpy(&dst[eq * 64 + e], &hi, 2);
        memcpy(&dst[256 + eq * 64 + e], &lo, 2);
    }
}

// ---------------- input GEMM via mma.sync (verified in R10) ----------------
#define XROWB 1040
#define XSCR  66560
__global__ void __launch_bounds__(THR, 1) xpre_mma_kernel(
    const float* __restrict__ Wf, const float* __restrict__ Wi,
    const float* __restrict__ Wc, const float* __restrict__ Wo,
    const float* __restrict__ bf, const float* __restrict__ bi,
    const float* __restrict__ bc, const float* __restrict__ bo)
{
    extern __shared__ char sm[];
    float* scr = (float*)(sm + XSCR);          // [64][264] padded

    const int tid = threadIdx.x, wid = tid >> 5, lane = tid & 31;
    const int nt = blockIdx.x, sg = blockIdx.y;
    const float* W4[4] = {Wf, Wi, Wc, Wo};
    const float* Bi4[4] = {bf, bi, bc, bo};

    uint32_t Bf[6][4][2];
#pragma unroll
    for (int kt = 0; kt < 6; ++kt)
#pragma unroll
        for (int nf = 0; nf < 4; ++nf) {
            int n = nf * 8 + (lane >> 2);
            int j = nt * 8 + (n >> 2);
            const float* Wg = W4[n & 3];
#pragma unroll
            for (int p = 0; p < 2; ++p) {
                int k1 = wid * 96 + kt * 16 + (lane & 3) * 2 + p * 8;
                int k2 = k1 + 1;
                float w1 = Wg[(size_t)(H_ + (k1 & 255)) * H_ + j];
                float w2 = Wg[(size_t)(H_ + (k2 & 255)) * H_ + j];
                unsigned short v1 = (k1 >= 512) ? bflo(w1) : bfhi(w1);
                unsigned short v2 = (k2 >= 512) ? bflo(w2) : bfhi(w2);
                Bf[kt][nf][p] = (uint32_t)v1 | ((uint32_t)v2 << 16);
            }
        }

    const int b = tid >> 2, up = tid & 3;
    float bq[8];
#pragma unroll
    for (int q = 0; q < 8; ++q) bq[q] = Bi4[q & 3][nt * 8 + up * 2 + (q >> 2)];

    const uint32_t smA = smem_u32(sm);
    const uint32_t lm_base = smA + (lane & 15) * XROWB + (lane >> 4) * 16;

    for (int si = 0; si < 16; ++si) {
        const int s = sg * 16 + si;
        {   // stage A via cp.async: 256B/thread
            const char* gsrc = (const char*)(g_embS + ((size_t)s * B_ + b) * 512) + up * 256;
            uint32_t sdst = smA + b * XROWB + up * 256;
#pragma unroll
            for (int c = 0; c < 16; ++c)
                CP_ASYNC16(sdst + c * 16, gsrc + c * 16);
            CP_COMMIT();
            CP_WAIT(0);
        }
        __syncthreads();

#pragma unroll
        for (int mh = 0; mh < 2; ++mh) {
            float acc[4][2][4];
#pragma unroll
            for (int nf = 0; nf < 4; ++nf)
#pragma unroll
                for (int m2 = 0; m2 < 2; ++m2) {
                    acc[nf][m2][0] = 0.f; acc[nf][m2][1] = 0.f;
                    acc[nf][m2][2] = 0.f; acc[nf][m2][3] = 0.f;
                }
#pragma unroll
            for (int kt = 0; kt < 6; ++kt) {
                uint32_t colB = (uint32_t)(((wid * 96 + kt * 16) & 511) * 2);
                uint32_t a[2][4];
#pragma unroll
                for (int m2 = 0; m2 < 2; ++m2)
                    LDSM4(a[m2], lm_base + (mh * 2 + m2) * 16 * XROWB + colB);
#pragma unroll
                for (int m2 = 0; m2 < 2; ++m2)
#pragma unroll
                    for (int nf = 0; nf < 4; ++nf)
                        MMA16816(acc[nf][m2], a[m2], Bf[kt][nf]);
            }
#pragma unroll
            for (int nf = 0; nf < 4; ++nf)
#pragma unroll
                for (int m2 = 0; m2 < 2; ++m2) {
                    int m = (mh * 2 + m2) * 16 + (lane >> 2);
                    int nn = nf * 8 + (lane & 3) * 2;
                    scr[m * 264 + wid * 32 + nn]           = acc[nf][m2][0];
                    scr[m * 264 + wid * 32 + nn + 1]       = acc[nf][m2][1];
                    scr[(m + 8) * 264 + wid * 32 + nn]     = acc[nf][m2][2];
                    scr[(m + 8) * 264 + wid * 32 + nn + 1] = acc[nf][m2][3];
                }
        }
        __syncthreads();

        float o[8];
#pragma unroll
        for (int q = 0; q < 8; ++q) {
            float ss = bq[q];
#pragma unroll
            for (int w8 = 0; w8 < 8; ++w8) ss += scr[b * 264 + w8 * 32 + up * 8 + q];
            o[q] = ss;
        }
        float* outp = g_xpre + ((size_t)s * B_ + b) * 2048 + nt * 32 + up * 8;
        *(float4*)(outp)     = make_float4(o[0], o[1], o[2], o[3]);
        *(float4*)(outp + 4) = make_float4(o[4], o[5], o[6], o[7]);
        __syncthreads();
    }
}

// ---------------- persistent recurrent LSTM via mma.sync, v2 ----------------
// 128 CTAs x 8 warps; CTA = 4 units (N=16 cols n=u*4+g). Warp = (mt, nh) M x N
// tile with FULL K (no cross-warp reduction). K' map: [0,512) hhi*Whi ;
// [512,1024) hlo*Whi ; [1024,1536) hhi*Wlo ; A smem col = k'&1023.
// B-fragments precomputed to SMEM per-lane; A staged via cp.async.cg in two
// commit groups (hhi first -> 64 kts overlap hlo arrival).
#define RROWB 2064
#define R_BF  132096                  // B-frag region offset (64*2064)
#define RSM   (132096 + 49152)        // + 2*96*32*8
__global__ void __launch_bounds__(THR, 1) lstm_mma2_kernel(
    const float* __restrict__ c_in,
    const float* __restrict__ Wf, const float* __restrict__ Wi,
    const float* __restrict__ Wc, const float* __restrict__ Wo,
    float* __restrict__ d_out)
{
    extern __shared__ char sm[];
    const int tid = threadIdx.x, wid = tid >> 5, lane = tid & 31;
    const int bx = blockIdx.x;
    const int j0 = bx * 4;
    const int mt = wid & 3, nh = wid >> 2;
    const float* W4[4] = {Wf, Wi, Wc, Wo};

    const uint32_t smA  = smem_u32(sm);

    // ---- prologue: B fragments (verified mapping) into SMEM per-lane ----
    for (int pair = wid; pair < 192; pair += 8) {
        int nh2 = pair / 96, ktt = pair % 96;
        int n = nh2 * 8 + (lane >> 2);
        int j = j0 + (n >> 2);
        const float* Wg = W4[n & 3];
        uint32_t fr[2];
#pragma unroll
        for (int p = 0; p < 2; ++p) {
            int k1 = ktt * 16 + (lane & 3) * 2 + p * 8;
            int k2 = k1 + 1;
            float w1 = Wg[(size_t)(k1 & 511) * H_ + j];
            float w2 = Wg[(size_t)(k2 & 511) * H_ + j];
            unsigned short v1 = (k1 >= 1024) ? bflo(w1) : bfhi(w1);
            unsigned short v2 = (k2 >= 1024) ? bflo(w2) : bfhi(w2);
            fr[p] = (uint32_t)v1 | ((uint32_t)v2 << 16);
        }
        *(uint2*)(sm + R_BF + ((size_t)(nh2 * 96 + ktt) * 32 + lane) * 8) =
            make_uint2(fr[0], fr[1]);
    }

    // thread -> (row_g, unit) ownership for epilogue / c-state
    const int t4 = lane & 3;
    const int row_g = mt * 16 + (lane >> 2) + 8 * (t4 & 1);
    const int u_loc = nh * 2 + (t4 >> 1);
    const int jg = j0 + u_loc;
    float cst = c_in[row_g * H_ + jg];

    // staging role: b row, quarter
    const int sb = tid >> 2, sq = tid & 3;
    const uint32_t lm_base = smA + (mt * 16 + (lane & 15)) * RROWB + (lane >> 4) * 16;

    __syncthreads();

    for (int s = 0; s < S_; ++s) {
        const int rbuf = s & 1;

        // xpre prefetch (step-static, before barrier)
        float4 xp = *(const float4*)(g_xpre + ((size_t)s * B_ + row_g) * 2048
                                     + bx * 16 + u_loc * 4);

        // flag barrier (R5 protocol, with backoff to cut L2 poll pressure)
        if (tid < NCTA) {
            const int* fl = &g_flag[tid * 32];
            while (ld_acquire_gpu(fl) < s + 1) { __nanosleep(32); }
        }
        __syncthreads();

        // stage split h via cp.async.cg: two groups (hhi, then hlo)
        {
            const char* gsrc = (const char*)(g_hA + rbuf * (B_ * 1024) + sb * 1024);
            uint32_t sdst = smA + sb * RROWB;
#pragma unroll
            for (int i = 0; i < 16; ++i)
                CP_ASYNC16(sdst + sq * 256 + i * 16, gsrc + sq * 256 + i * 16);
            CP_COMMIT();
#pragma unroll
            for (int i = 0; i < 16; ++i)
                CP_ASYNC16(sdst + 1024 + sq * 256 + i * 16, gsrc + 1024 + sq * 256 + i * 16);
            CP_COMMIT();
        }

        float d[4] = {0.f, 0.f, 0.f, 0.f};

        // phase 1: hhi terms (kts 0..31 = hhi*Whi, 64..95 = hhi*Wlo)
        CP_WAIT(1);
        __syncthreads();
#pragma unroll 8
        for (int kt = 0; kt < 64; ++kt) {
            int ktt = (kt < 32) ? kt : kt + 32;
            uint32_t acol = (uint32_t)(((ktt * 16) & 1023) * 2);
            uint32_t a[4];
            LDSM4(a, lm_base + acol);
            uint2 bv = *(const uint2*)(sm + R_BF + ((size_t)(nh * 96 + ktt) * 32 + lane) * 8);
            uint32_t bb[2] = {bv.x, bv.y};
            MMA16816(d, a, bb);
        }
        // phase 2: hlo terms (kts 32..63 = hlo*Whi)
        CP_WAIT(0);
        __syncthreads();
#pragma unroll 8
        for (int ktt = 32; ktt < 64; ++ktt) {
            uint32_t acol = (uint32_t)(ktt * 32);
            uint32_t a[4];
            LDSM4(a, lm_base + acol);
            uint2 bv = *(const uint2*)(sm + R_BF + ((size_t)(nh * 96 + ktt) * 32 + lane) * 8);
            uint32_t bb[2] = {bv.x, bv.y};
            MMA16816(d, a, bb);
        }

        // epilogue: pair exchange -> 4 gates per (row_g, unit)
        float o0 = __shfl_xor_sync(0xFFFFFFFFu, d[0], 1);
        float o1 = __shfl_xor_sync(0xFFFFFFFFu, d[1], 1);
        float o2 = __shfl_xor_sync(0xFFFFFFFFu, d[2], 1);
        float o3 = __shfl_xor_sync(0xFFFFFFFFu, d[3], 1);
        float gf, gi, gc, go;
        if ((t4 & 1) == 0) { gf = d[0]; gi = d[1]; gc = o0; go = o1; }  // row r
        else               { gf = o2;  gi = o3;  gc = d[2]; go = d[3]; } // row r+8

        float pf = gf + xp.x, pi = gi + xp.y, pc = gc + xp.z, po = go + xp.w;
        float f = sigf(pf), i = sigf(pi), g = tanhf_fast(pc), o = sigf(po);
        cst = f * cst + i * g;
        float h = o * tanhf_fast(cst);

        if (s < S_ - 1) {
            const int wb = rbuf ^ 1;
            unsigned short hh = bfhi(h), hl = bflo(h);
            __nv_bfloat16* dst = g_hA + wb * (B_ * 1024) + row_g * 1024;
            *(unsigned short*)&dst[jg]       = hh;
            *(unsigned short*)&dst[512 + jg] = hl;
            __threadfence();
            __syncthreads();
            if (tid == 0) st_release_gpu(&g_flag[bx * 32], s + 2);
        } else {
            d_out[B_ * O_ + row_g * H_ + jg] = h;
        }
    }
}

// ---------------- dense head ----------------
__global__ void __launch_bounds__(256) dense_out_kernel(
    const float* __restrict__ Wd, const float* __restrict__ bd,
    float* __restrict__ d_out)
{
    const int o  = blockIdx.x * 256 + threadIdx.x;
    const int b0 = blockIdx.y * 2;
    __shared__ float sh[2][H_];
    const float* hsrc = d_out + B_ * O_;
    for (int idx = threadIdx.x; idx < 2 * H_; idx += 256) {
        int bi = idx >> 9, j = idx & (H_ - 1);
        sh[bi][j] = hsrc[(b0 + bi) * H_ + j];
    }
    __syncthreads();
    if (o < O_) {
        float bias = bd[o];
        float acc0 = bias, acc1 = bias;
#pragma unroll 8
        for (int j = 0; j < H_; ++j) {
            float wv = Wd[(size_t)j * O_ + o];
            acc0 += sh[0][j] * wv;
            acc1 += sh[1][j] * wv;
        }
        d_out[(b0 + 0) * O_ + o] = acc0;
        d_out[(b0 + 1) * O_ + o] = acc1;
    }
}

// ---------------- launch ----------------
extern "C" void kernel_launch(void* const* d_in, const int* in_sizes, int n_in,
                              void* d_out, int out_size) {
    const int*   x        = (const int*)  d_in[0];
    const float* hidden   = (const float*)d_in[1];
    const float* c        = (const float*)d_in[2];
    const float* embed_w  = (const float*)d_in[3];
    const float* W_f      = (const float*)d_in[4];
    const float* b_f      = (const float*)d_in[5];
    const float* W_i      = (const float*)d_in[6];
    const float* b_i      = (const float*)d_in[7];
    const float* W_c      = (const float*)d_in[8];
    const float* b_c      = (const float*)d_in[9];
    const float* W_o      = (const float*)d_in[10];
    const float* b_o      = (const float*)d_in[11];
    const float* W_d      = (const float*)d_in[12];
    const float* b_d      = (const float*)d_in[13];
    float* out = (float*)d_out;

    static bool attr_set = false;
    if (!attr_set) {
        cudaFuncSetAttribute(xpre_mma_kernel,
                             cudaFuncAttributeMaxDynamicSharedMemorySize, XSCR + 67584);
        cudaFuncSetAttribute(lstm_mma2_kernel,
                             cudaFuncAttributeMaxDynamicSharedMemorySize, RSM);
        attr_set = true;
    }

    init_flags_kernel<<<1, NCTA>>>();
    a0_prep_kernel<<<(B_ * H_ + 255) / 256, 256>>>(hidden);
    embs_prep_kernel<<<S_, 256>>>(x, embed_w);

    dim3 gx(64, 32);
    xpre_mma_kernel<<<gx, THR, XSCR + 67584>>>(W_f, W_i, W_c, W_o, b_f, b_i, b_c, b_o);

    lstm_mma2_kernel<<<NCTA, THR, RSM>>>(c, W_f, W_i, W_c, W_o, out);

    dim3 g3(4, 32);
    dense_out_kernel<<<g3, 256>>>(W_d, b_d, out);
}

// round 14
// speedup vs baseline: 1.2478x; 1.0554x over previous
#include <cuda_runtime.h>
#include <cuda_bf16.h>
#include <cstdint>
#include <math.h>

#define B_   64
#define S_   512
#define E_   256
#define H_   512
#define O_   1000
#define NBLK 128
#define THR  256

// ---------------- device scratch ----------------
__device__ float g_h[2 * H_ * B_];                      // [buf][j][b] fp32
__device__ __nv_bfloat16 g_embS[(size_t)S_ * B_ * 512]; // [s][b][k] k: hi[0,256) lo[256,512)
__device__ float g_xpre[(size_t)S_ * B_ * 2048];        // [s][b][col], col=j*4+g, bias folded
__device__ int   g_flag[NBLK * 32];

// ---------------- helpers ----------------
__device__ __forceinline__ int ld_acquire_gpu(const int* p) {
    int v; asm volatile("ld.acquire.gpu.global.s32 %0, [%1];" : "=r"(v) : "l"(p) : "memory");
    return v;
}
__device__ __forceinline__ void st_release_gpu(int* p, int v) {
    asm volatile("st.release.gpu.global.s32 [%0], %1;" :: "l"(p), "r"(v) : "memory");
}
__device__ __forceinline__ float sigf(float v) { return __fdividef(1.f, 1.f + __expf(-v)); }
__device__ __forceinline__ float tanhf_fast(float v) { return __fdividef(2.f, 1.f + __expf(-2.f * v)) - 1.f; }
__device__ __forceinline__ unsigned short bfhi(float w) {
    __nv_bfloat16 h = __float2bfloat16(w); unsigned short u; memcpy(&u, &h, 2); return u;
}
__device__ __forceinline__ unsigned short bflo(float w) {
    __nv_bfloat16 h = __float2bfloat16(w);
    __nv_bfloat16 l = __float2bfloat16(w - __bfloat162float(h));
    unsigned short u; memcpy(&u, &l, 2); return u;
}
__device__ __forceinline__ uint32_t smem_u32(const void* p) {
    uint32_t a;
    asm("{ .reg .u64 t; cvta.to.shared.u64 t, %1; cvt.u32.u64 %0, t; }" : "=r"(a) : "l"(p));
    return a;
}
#define LDSM4(r, addr) \
    asm volatile("ldmatrix.sync.aligned.m8n8.x4.shared.b16 {%0,%1,%2,%3}, [%4];" \
        : "=r"((r)[0]), "=r"((r)[1]), "=r"((r)[2]), "=r"((r)[3]) : "r"(addr))
#define MMA16816(d, a, bb) \
    asm volatile("mma.sync.aligned.m16n8k16.row.col.f32.bf16.bf16.f32 " \
        "{%0,%1,%2,%3},{%4,%5,%6,%7},{%8,%9},{%0,%1,%2,%3};" \
        : "+f"((d)[0]), "+f"((d)[1]), "+f"((d)[2]), "+f"((d)[3]) \
        : "r"((a)[0]), "r"((a)[1]), "r"((a)[2]), "r"((a)[3]), "r"((bb)[0]), "r"((bb)[1]))
#define CP_ASYNC16(dst, src) \
    asm volatile("cp.async.cg.shared.global [%0], [%1], 16;" :: "r"(dst), "l"(src) : "memory")
#define CP_COMMIT() asm volatile("cp.async.commit_group;" ::: "memory")
#define CP_WAIT(n)  asm volatile("cp.async.wait_group %0;" :: "n"(n) : "memory")

__global__ void init_flags_kernel() { g_flag[threadIdx.x * 32] = 0; }

// ---------------- prep: embedding gather + split ----------------
__global__ void __launch_bounds__(256) embs_prep_kernel(
    const int* __restrict__ x, const float* __restrict__ embed_w) {
    const int s = blockIdx.x, t = threadIdx.x;
    const int b = t >> 2, eq = t & 3;
    const int row = x[b * S_ + s];
    const float* src = embed_w + (size_t)row * E_ + eq * 64;
    __nv_bfloat16* dst = g_embS + ((size_t)s * B_ + b) * 512;
#pragma unroll 8
    for (int e = 0; e < 64; ++e) {
        float w = src[e];
        unsigned short hi = bfhi(w), lo = bflo(w);
        memcpy(&dst[eq * 64 + e], &hi, 2);
        memcpy(&dst[256 + eq * 64 + e], &lo, 2);
    }
}

// ---------------- input GEMM via mma.sync (verified R10/R12) ----------------
#define XROWB 1040
#define XSCR  66560
__global__ void __launch_bounds__(THR, 1) xpre_mma_kernel(
    const float* __restrict__ Wf, const float* __restrict__ Wi,
    const float* __restrict__ Wc, const float* __restrict__ Wo,
    const float* __restrict__ bf, const float* __restrict__ bi,
    const float* __restrict__ bc, const float* __restrict__ bo)
{
    extern __shared__ char sm[];
    float* scr = (float*)(sm + XSCR);          // [64][264] padded

    const int tid = threadIdx.x, wid = tid >> 5, lane = tid & 31;
    const int nt = blockIdx.x, sg = blockIdx.y;
    const float* W4[4] = {Wf, Wi, Wc, Wo};
    const float* Bi4[4] = {bf, bi, bc, bo};

    uint32_t Bf[6][4][2];
#pragma unroll
    for (int kt = 0; kt < 6; ++kt)
#pragma unroll
        for (int nf = 0; nf < 4; ++nf) {
            int n = nf * 8 + (lane >> 2);
            int j = nt * 8 + (n >> 2);
            const float* Wg = W4[n & 3];
#pragma unroll
            for (int p = 0; p < 2; ++p) {
                int k1 = wid * 96 + kt * 16 + (lane & 3) * 2 + p * 8;
                int k2 = k1 + 1;
                float w1 = Wg[(size_t)(H_ + (k1 & 255)) * H_ + j];
                float w2 = Wg[(size_t)(H_ + (k2 & 255)) * H_ + j];
                unsigned short v1 = (k1 >= 512) ? bflo(w1) : bfhi(w1);
                unsigned short v2 = (k2 >= 512) ? bflo(w2) : bfhi(w2);
                Bf[kt][nf][p] = (uint32_t)v1 | ((uint32_t)v2 << 16);
            }
        }

    const int b = tid >> 2, up = tid & 3;
    float bq[8];
#pragma unroll
    for (int q = 0; q < 8; ++q) bq[q] = Bi4[q & 3][nt * 8 + up * 2 + (q >> 2)];

    const uint32_t smA = smem_u32(sm);
    const uint32_t lm_base = smA + (lane & 15) * XROWB + (lane >> 4) * 16;

    for (int si = 0; si < 16; ++si) {
        const int s = sg * 16 + si;
        {
            const char* gsrc = (const char*)(g_embS + ((size_t)s * B_ + b) * 512) + up * 256;
            uint32_t sdst = smA + b * XROWB + up * 256;
#pragma unroll
            for (int c = 0; c < 16; ++c)
                CP_ASYNC16(sdst + c * 16, gsrc + c * 16);
            CP_COMMIT();
            CP_WAIT(0);
        }
        __syncthreads();

#pragma unroll
        for (int mh = 0; mh < 2; ++mh) {
            float acc[4][2][4];
#pragma unroll
            for (int nf = 0; nf < 4; ++nf)
#pragma unroll
                for (int m2 = 0; m2 < 2; ++m2) {
                    acc[nf][m2][0] = 0.f; acc[nf][m2][1] = 0.f;
                    acc[nf][m2][2] = 0.f; acc[nf][m2][3] = 0.f;
                }
#pragma unroll
            for (int kt = 0; kt < 6; ++kt) {
                uint32_t colB = (uint32_t)(((wid * 96 + kt * 16) & 511) * 2);
                uint32_t a[2][4];
#pragma unroll
                for (int m2 = 0; m2 < 2; ++m2)
                    LDSM4(a[m2], lm_base + (mh * 2 + m2) * 16 * XROWB + colB);
#pragma unroll
                for (int m2 = 0; m2 < 2; ++m2)
#pragma unroll
                    for (int nf = 0; nf < 4; ++nf)
                        MMA16816(acc[nf][m2], a[m2], Bf[kt][nf]);
            }
#pragma unroll
            for (int nf = 0; nf < 4; ++nf)
#pragma unroll
                for (int m2 = 0; m2 < 2; ++m2) {
                    int m = (mh * 2 + m2) * 16 + (lane >> 2);
                    int nn = nf * 8 + (lane & 3) * 2;
                    scr[m * 264 + wid * 32 + nn]           = acc[nf][m2][0];
                    scr[m * 264 + wid * 32 + nn + 1]       = acc[nf][m2][1];
                    scr[(m + 8) * 264 + wid * 32 + nn]     = acc[nf][m2][2];
                    scr[(m + 8) * 264 + wid * 32 + nn + 1] = acc[nf][m2][3];
                }
        }
        __syncthreads();

        float o[8];
#pragma unroll
        for (int q = 0; q < 8; ++q) {
            float ss = bq[q];
#pragma unroll
            for (int w8 = 0; w8 < 8; ++w8) ss += scr[b * 264 + w8 * 32 + up * 8 + q];
            o[q] = ss;
        }
        float* outp = g_xpre + ((size_t)s * B_ + b) * 2048 + nt * 32 + up * 8;
        *(float4*)(outp)     = make_float4(o[0], o[1], o[2], o[3]);
        *(float4*)(outp + 4) = make_float4(o[4], o[5], o[6], o[7]);
        __syncthreads();
    }
}

// ---------------- persistent scalar recurrent LSTM, v3 ----------------
// 128 CTAs x 256 thr; CTA owns 4 units (16 gate cols). wu=wid&3 -> unit,
// kh=wid>>2 -> K-half, lane -> batches 2l,2l+1. Weights fp32 in SMEM (once).
// h chunks (16KB) double-buffered via cp.async.cg, overlapped with FFMA.
// Flag sync = R5 proven acquire/release protocol (plain spin).
// SMEM: sWh 32KB | sH 2x16KB | red 4KB = 69632 B dynamic.
#define V3_SWH 0
#define V3_SH  32768
#define V3_RED 65536
#define V3_SM  69632
__global__ void __launch_bounds__(THR, 1) lstm_scalar3_kernel(
    const float* __restrict__ hidden_in, const float* __restrict__ c_in,
    const float* __restrict__ Wf, const float* __restrict__ Wi,
    const float* __restrict__ Wc, const float* __restrict__ Wo,
    float* __restrict__ d_out)
{
    extern __shared__ char smraw[];
    float* sWh = (float*)(smraw + V3_SWH);   // [k][jj*4+g]
    float* red = (float*)(smraw + V3_RED);
    const uint32_t smH = smem_u32(smraw) + V3_SH;

    const int tid  = threadIdx.x;
    const int wid  = tid >> 5;
    const int lane = tid & 31;
    const int wu   = wid & 3;
    const int kh   = wid >> 2;
    const int j0   = blockIdx.x * 4;
    const int jme  = j0 + wu;
    const int b0   = lane * 2;

    const float* W4[4] = {Wf, Wi, Wc, Wo};
    for (int k = tid; k < H_; k += THR) {
#pragma unroll
        for (int jj = 0; jj < 4; ++jj)
#pragma unroll
            for (int g = 0; g < 4; ++g)
                sWh[k * 16 + jj * 4 + g] = W4[g][(size_t)k * H_ + j0 + jj];
    }

    float c0 = 0.f, c1 = 0.f;
    if (kh == 0) {
        c0 = c_in[(b0 + 0) * H_ + jme];
        c1 = c_in[(b0 + 1) * H_ + jme];
        g_h[jme * B_ + b0 + 0] = hidden_in[(b0 + 0) * H_ + jme];
        g_h[jme * B_ + b0 + 1] = hidden_in[(b0 + 1) * H_ + jme];
    }
    __threadfence();
    __syncthreads();
    if (tid == 0) st_release_gpu(&g_flag[blockIdx.x * 32], 1);

    for (int s = 0; s < S_; ++s) {
        const int rbuf = s & 1;
        const char* hsrc = (const char*)(g_h + rbuf * (H_ * B_));

        // xpre prefetch (step-static, before the barrier)
        float4 xpa = make_float4(0.f, 0.f, 0.f, 0.f);
        float4 xpb = xpa;
        if (kh == 0) {
            const float* xb = g_xpre + (size_t)s * B_ * 2048 + jme * 4;
            xpa = *(const float4*)(xb + (size_t)(b0 + 0) * 2048);
            xpb = *(const float4*)(xb + (size_t)(b0 + 1) * 2048);
        }

        // flag barrier
        if (tid < NBLK) {
            const int* fl = &g_flag[tid * 32];
            while (ld_acquire_gpu(fl) < s + 1) { }
        }
        __syncthreads();

        // stage chunk 0
        {
            uint32_t sdst = smH + tid * 64;
            const char* gp = hsrc + tid * 64;
#pragma unroll
            for (int i = 0; i < 4; ++i) CP_ASYNC16(sdst + i * 16, gp + i * 16);
            CP_COMMIT();
        }

        float acc[8] = {0.f, 0.f, 0.f, 0.f, 0.f, 0.f, 0.f, 0.f};
        for (int c = 0; c < 8; ++c) {
            CP_WAIT(0);
            __syncthreads();     // chunk c visible; compute(c-1) on other buf done
            if (c < 7) {         // stage chunk c+1 into other buffer
                uint32_t sdst = smH + ((c + 1) & 1) * 16384 + tid * 64;
                const char* gp = hsrc + (c + 1) * 16384 + tid * 64;
#pragma unroll
                for (int i = 0; i < 4; ++i) CP_ASYNC16(sdst + i * 16, gp + i * 16);
                CP_COMMIT();
            }
            const float* hb = (const float*)(smraw + V3_SH + (c & 1) * 16384)
                              + kh * 32 * 64 + b0;
            const float* wv0 = sWh + (c * 64 + kh * 32) * 16 + wu * 4;
#pragma unroll 32
            for (int kk = 0; kk < 32; ++kk) {
                float2 hv = *(const float2*)(hb + kk * 64);
                float4 wv = *(const float4*)(wv0 + kk * 16);
                acc[0] += hv.x * wv.x; acc[1] += hv.x * wv.y;
                acc[2] += hv.x * wv.z; acc[3] += hv.x * wv.w;
                acc[4] += hv.y * wv.x; acc[5] += hv.y * wv.y;
                acc[6] += hv.y * wv.z; acc[7] += hv.y * wv.w;
            }
        }

        // reduce K-halves
        if (kh == 1) {
            float* p = red + (wu * 32 + lane) * 8;
#pragma unroll
            for (int i = 0; i < 8; ++i) p[i] = acc[i];
        }
        __syncthreads();
        if (kh == 0) {
            const float* p = red + (wu * 32 + lane) * 8;
#pragma unroll
            for (int i = 0; i < 8; ++i) acc[i] += p[i];

            float f0 = sigf(acc[0] + xpa.x), i0 = sigf(acc[1] + xpa.y);
            float g0 = tanhf_fast(acc[2] + xpa.z), o0 = sigf(acc[3] + xpa.w);
            c0 = f0 * c0 + i0 * g0;
            float h0 = o0 * tanhf_fast(c0);
            float f1 = sigf(acc[4] + xpb.x), i1 = sigf(acc[5] + xpb.y);
            float g1 = tanhf_fast(acc[6] + xpb.z), o1 = sigf(acc[7] + xpb.w);
            c1 = f1 * c1 + i1 * g1;
            float h1 = o1 * tanhf_fast(c1);

            if (s < S_ - 1) {
                *(float2*)&g_h[(rbuf ^ 1) * (H_ * B_) + jme * B_ + b0] =
                    make_float2(h0, h1);
            } else {
                d_out[B_ * O_ + (b0 + 0) * H_ + jme] = h0;
                d_out[B_ * O_ + (b0 + 1) * H_ + jme] = h1;
            }
        }
        if (s < S_ - 1) {
            __threadfence();
            __syncthreads();
            if (tid == 0) st_release_gpu(&g_flag[blockIdx.x * 32], s + 2);
        }
    }
}

// ---------------- dense head ----------------
__global__ void __launch_bounds__(256) dense_out_kernel(
    const float* __restrict__ Wd, const float* __restrict__ bd,
    float* __restrict__ d_out)
{
    const int o  = blockIdx.x * 256 + threadIdx.x;
    const int b0 = blockIdx.y * 2;
    __shared__ float sh[2][H_];
    const float* hsrc = d_out + B_ * O_;
    for (int idx = threadIdx.x; idx < 2 * H_; idx += 256) {
        int bi = idx >> 9, j = idx & (H_ - 1);
        sh[bi][j] = hsrc[(b0 + bi) * H_ + j];
    }
    __syncthreads();
    if (o < O_) {
        float bias = bd[o];
        float acc0 = bias, acc1 = bias;
#pragma unroll 8
        for (int j = 0; j < H_; ++j) {
            float wv = Wd[(size_t)j * O_ + o];
            acc0 += sh[0][j] * wv;
            acc1 += sh[1][j] * wv;
        }
        d_out[(b0 + 0) * O_ + o] = acc0;
        d_out[(b0 + 1) * O_ + o] = acc1;
    }
}

// ---------------- launch ----------------
extern "C" void kernel_launch(void* const* d_in, const int* in_sizes, int n_in,
                              void* d_out, int out_size) {
    const int*   x        = (const int*)  d_in[0];
    const float* hidden   = (const float*)d_in[1];
    const float* c        = (const float*)d_in[2];
    const float* embed_w  = (const float*)d_in[3];
    const float* W_f      = (const float*)d_in[4];
    const float* b_f      = (const float*)d_in[5];
    const float* W_i      = (const float*)d_in[6];
    const float* b_i      = (const float*)d_in[7];
    const float* W_c      = (const float*)d_in[8];
    const float* b_c      = (const float*)d_in[9];
    const float* W_o      = (const float*)d_in[10];
    const float* b_o      = (const float*)d_in[11];
    const float* W_d      = (const float*)d_in[12];
    const float* b_d      = (const float*)d_in[13];
    float* out = (float*)d_out;

    static bool attr_set = false;
    if (!attr_set) {
        cudaFuncSetAttribute(xpre_mma_kernel,
                             cudaFuncAttributeMaxDynamicSharedMemorySize, XSCR + 67584);
        cudaFuncSetAttribute(lstm_scalar3_kernel,
                             cudaFuncAttributeMaxDynamicSharedMemorySize, V3_SM);
        attr_set = true;
    }

    init_flags_kernel<<<1, NBLK>>>();
    embs_prep_kernel<<<S_, 256>>>(x, embed_w);

    dim3 gx(64, 32);
    xpre_mma_kernel<<<gx, THR, XSCR + 67584>>>(W_f, W_i, W_c, W_o, b_f, b_i, b_c, b_o);

    lstm_scalar3_kernel<<<NBLK, THR, V3_SM>>>(hidden, c, W_f, W_i, W_c, W_o, out);

    dim3 g3(4, 32);
    dense_out_kernel<<<g3, 256>>>(W_d, b_d, out);
}

// round 15
// speedup vs baseline: 1.3406x; 1.0744x over previous
#include <cuda_runtime.h>
#include <cuda_bf16.h>
#include <cstdint>
#include <math.h>

#define B_   64
#define S_   512
#define E_   256
#define H_   512
#define O_   1000
#define NBLK 128
#define THR  256

// ---------------- device scratch ----------------
__device__ float g_h[2 * H_ * B_];                      // [buf][j][b] fp32
__device__ __nv_bfloat16 g_embS[(size_t)S_ * B_ * 512]; // [s][b][k] k: hi[0,256) lo[256,512)
__device__ float g_xpre[(size_t)S_ * B_ * 2048];        // [s][b][col], col=j*4+g, bias folded
__device__ int   g_flag[NBLK * 32];

// ---------------- helpers ----------------
__device__ __forceinline__ int ld_acquire_gpu(const int* p) {
    int v; asm volatile("ld.acquire.gpu.global.s32 %0, [%1];" : "=r"(v) : "l"(p) : "memory");
    return v;
}
__device__ __forceinline__ void st_release_gpu(int* p, int v) {
    asm volatile("st.release.gpu.global.s32 [%0], %1;" :: "l"(p), "r"(v) : "memory");
}
__device__ __forceinline__ float sigf(float v) { return __fdividef(1.f, 1.f + __expf(-v)); }
__device__ __forceinline__ float tanhf_fast(float v) { return __fdividef(2.f, 1.f + __expf(-2.f * v)) - 1.f; }
__device__ __forceinline__ unsigned short bfhi(float w) {
    __nv_bfloat16 h = __float2bfloat16(w); unsigned short u; memcpy(&u, &h, 2); return u;
}
__device__ __forceinline__ unsigned short bflo(float w) {
    __nv_bfloat16 h = __float2bfloat16(w);
    __nv_bfloat16 l = __float2bfloat16(w - __bfloat162float(h));
    unsigned short u; memcpy(&u, &l, 2); return u;
}
__device__ __forceinline__ uint32_t smem_u32(const void* p) {
    uint32_t a;
    asm("{ .reg .u64 t; cvta.to.shared.u64 t, %1; cvt.u32.u64 %0, t; }" : "=r"(a) : "l"(p));
    return a;
}
#define LDSM4(r, addr) \
    asm volatile("ldmatrix.sync.aligned.m8n8.x4.shared.b16 {%0,%1,%2,%3}, [%4];" \
        : "=r"((r)[0]), "=r"((r)[1]), "=r"((r)[2]), "=r"((r)[3]) : "r"(addr))
#define MMA16816(d, a, bb) \
    asm volatile("mma.sync.aligned.m16n8k16.row.col.f32.bf16.bf16.f32 " \
        "{%0,%1,%2,%3},{%4,%5,%6,%7},{%8,%9},{%0,%1,%2,%3};" \
        : "+f"((d)[0]), "+f"((d)[1]), "+f"((d)[2]), "+f"((d)[3]) \
        : "r"((a)[0]), "r"((a)[1]), "r"((a)[2]), "r"((a)[3]), "r"((bb)[0]), "r"((bb)[1]))
#define CP_ASYNC16(dst, src) \
    asm volatile("cp.async.cg.shared.global [%0], [%1], 16;" :: "r"(dst), "l"(src) : "memory")
#define CP_COMMIT() asm volatile("cp.async.commit_group;" ::: "memory")
#define CP_WAIT(n)  asm volatile("cp.async.wait_group %0;" :: "n"(n) : "memory")

__global__ void init_flags_kernel() { g_flag[threadIdx.x * 32] = 0; }

// ---------------- prep: embedding gather + split ----------------
__global__ void __launch_bounds__(256) embs_prep_kernel(
    const int* __restrict__ x, const float* __restrict__ embed_w) {
    const int s = blockIdx.x, t = threadIdx.x;
    const int b = t >> 2, eq = t & 3;
    const int row = x[b * S_ + s];
    const float* src = embed_w + (size_t)row * E_ + eq * 64;
    __nv_bfloat16* dst = g_embS + ((size_t)s * B_ + b) * 512;
#pragma unroll 8
    for (int e = 0; e < 64; ++e) {
        float w = src[e];
        unsigned short hi = bfhi(w), lo = bflo(w);
        memcpy(&dst[eq * 64 + e], &hi, 2);
        memcpy(&dst[256 + eq * 64 + e], &lo, 2);
    }
}

// ---------------- input GEMM via mma.sync (verified R10/R12/R14) ----------------
#define XROWB 1040
#define XSCR  66560
__global__ void __launch_bounds__(THR, 1) xpre_mma_kernel(
    const float* __restrict__ Wf, const float* __restrict__ Wi,
    const float* __restrict__ Wc, const float* __restrict__ Wo,
    const float* __restrict__ bf, const float* __restrict__ bi,
    const float* __restrict__ bc, const float* __restrict__ bo)
{
    extern __shared__ char sm[];
    float* scr = (float*)(sm + XSCR);          // [64][264] padded

    const int tid = threadIdx.x, wid = tid >> 5, lane = tid & 31;
    const int nt = blockIdx.x, sg = blockIdx.y;
    const float* W4[4] = {Wf, Wi, Wc, Wo};
    const float* Bi4[4] = {bf, bi, bc, bo};

    uint32_t Bf[6][4][2];
#pragma unroll
    for (int kt = 0; kt < 6; ++kt)
#pragma unroll
        for (int nf = 0; nf < 4; ++nf) {
            int n = nf * 8 + (lane >> 2);
            int j = nt * 8 + (n >> 2);
            const float* Wg = W4[n & 3];
#pragma unroll
            for (int p = 0; p < 2; ++p) {
                int k1 = wid * 96 + kt * 16 + (lane & 3) * 2 + p * 8;
                int k2 = k1 + 1;
                float w1 = Wg[(size_t)(H_ + (k1 & 255)) * H_ + j];
                float w2 = Wg[(size_t)(H_ + (k2 & 255)) * H_ + j];
                unsigned short v1 = (k1 >= 512) ? bflo(w1) : bfhi(w1);
                unsigned short v2 = (k2 >= 512) ? bflo(w2) : bfhi(w2);
                Bf[kt][nf][p] = (uint32_t)v1 | ((uint32_t)v2 << 16);
            }
        }

    const int b = tid >> 2, up = tid & 3;
    float bq[8];
#pragma unroll
    for (int q = 0; q < 8; ++q) bq[q] = Bi4[q & 3][nt * 8 + up * 2 + (q >> 2)];

    const uint32_t smA = smem_u32(sm);
    const uint32_t lm_base = smA + (lane & 15) * XROWB + (lane >> 4) * 16;

    for (int si = 0; si < 16; ++si) {
        const int s = sg * 16 + si;
        {
            const char* gsrc = (const char*)(g_embS + ((size_t)s * B_ + b) * 512) + up * 256;
            uint32_t sdst = smA + b * XROWB + up * 256;
#pragma unroll
            for (int c = 0; c < 16; ++c)
                CP_ASYNC16(sdst + c * 16, gsrc + c * 16);
            CP_COMMIT();
            CP_WAIT(0);
        }
        __syncthreads();

#pragma unroll
        for (int mh = 0; mh < 2; ++mh) {
            float acc[4][2][4];
#pragma unroll
            for (int nf = 0; nf < 4; ++nf)
#pragma unroll
                for (int m2 = 0; m2 < 2; ++m2) {
                    acc[nf][m2][0] = 0.f; acc[nf][m2][1] = 0.f;
                    acc[nf][m2][2] = 0.f; acc[nf][m2][3] = 0.f;
                }
#pragma unroll
            for (int kt = 0; kt < 6; ++kt) {
                uint32_t colB = (uint32_t)(((wid * 96 + kt * 16) & 511) * 2);
                uint32_t a[2][4];
#pragma unroll
                for (int m2 = 0; m2 < 2; ++m2)
                    LDSM4(a[m2], lm_base + (mh * 2 + m2) * 16 * XROWB + colB);
#pragma unroll
                for (int m2 = 0; m2 < 2; ++m2)
#pragma unroll
                    for (int nf = 0; nf < 4; ++nf)
                        MMA16816(acc[nf][m2], a[m2], Bf[kt][nf]);
            }
#pragma unroll
            for (int nf = 0; nf < 4; ++nf)
#pragma unroll
                for (int m2 = 0; m2 < 2; ++m2) {
                    int m = (mh * 2 + m2) * 16 + (lane >> 2);
                    int nn = nf * 8 + (lane & 3) * 2;
                    scr[m * 264 + wid * 32 + nn]           = acc[nf][m2][0];
                    scr[m * 264 + wid * 32 + nn + 1]       = acc[nf][m2][1];
                    scr[(m + 8) * 264 + wid * 32 + nn]     = acc[nf][m2][2];
                    scr[(m + 8) * 264 + wid * 32 + nn + 1] = acc[nf][m2][3];
                }
        }
        __syncthreads();

        float o[8];
#pragma unroll
        for (int q = 0; q < 8; ++q) {
            float ss = bq[q];
#pragma unroll
            for (int w8 = 0; w8 < 8; ++w8) ss += scr[b * 264 + w8 * 32 + up * 8 + q];
            o[q] = ss;
        }
        float* outp = g_xpre + ((size_t)s * B_ + b) * 2048 + nt * 32 + up * 8;
        *(float4*)(outp)     = make_float4(o[0], o[1], o[2], o[3]);
        *(float4*)(outp + 4) = make_float4(o[4], o[5], o[6], o[7]);
        __syncthreads();
    }
}

// ---------------- persistent recurrent LSTM (R5 core, proven 8.3us/step) ----
// 128 CTAs x 128 threads; CTA owns 4 hidden units (16 gate cols), weights in SMEM.
// warp w -> hidden unit j0+w; lane l -> batches 2l, 2l+1. c state in registers.
// Flag sync = R5 acquire/release protocol. xpre read in [s][b][col] layout.
__global__ void __launch_bounds__(128, 1) lstm_persistent_kernel(
    const float* __restrict__ hidden_in, const float* __restrict__ c_in,
    const float* __restrict__ Wf, const float* __restrict__ Wi,
    const float* __restrict__ Wc, const float* __restrict__ Wo,
    float* __restrict__ d_out)
{
    __shared__ float sWh[512][16];   // [k][jj*4 + g], g order {f,i,c,o}  (32 KB)
    __shared__ float sH[64][64];     // [k_local][b]                       (16 KB)

    const int tid  = threadIdx.x;
    const int w    = tid >> 5;
    const int lane = tid & 31;
    const int j0   = blockIdx.x * 4;
    const int jme  = j0 + w;
    const int b0   = lane * 2;

    const float* W4[4] = {Wf, Wi, Wc, Wo};
    for (int k = tid; k < H_; k += 128) {
#pragma unroll
        for (int jj = 0; jj < 4; ++jj)
#pragma unroll
            for (int g = 0; g < 4; ++g)
                sWh[k][jj * 4 + g] = W4[g][(size_t)k * H_ + j0 + jj];
    }

    // Initial state: publish h_0 and flag = 1
    float c0 = c_in[(b0 + 0) * H_ + jme];
    float c1 = c_in[(b0 + 1) * H_ + jme];
    g_h[jme * B_ + b0 + 0] = hidden_in[(b0 + 0) * H_ + jme];
    g_h[jme * B_ + b0 + 1] = hidden_in[(b0 + 1) * H_ + jme];
    __threadfence();
    __syncthreads();
    if (tid == 0) st_release_gpu(&g_flag[blockIdx.x * 32], 1);

    for (int s = 0; s < S_; ++s) {
        const int rbuf = s & 1;
        const int wbuf = rbuf ^ 1;
        const int target = s + 1;
        const float* hsrc = g_h + rbuf * (H_ * B_);

        // prefetch precomputed input part, [s][b][col] layout (step-static)
        float4 xpa, xpb;
        {
            const float* xb = g_xpre + ((size_t)s * B_ + b0) * 2048 + jme * 4;
            xpa = *(const float4*)xb;           // batch b0:   f,i,c,o
            xpb = *(const float4*)(xb + 2048);  // batch b0+1: f,i,c,o
        }

        // full step barrier: thread t acquires flag of CTA t
        {
            const int* fl = &g_flag[tid * 32];
            while (ld_acquire_gpu(fl) < target) { }
        }
        __syncthreads();

        // prefetch chunk 0 (L2-only loads: no stale L1)
        float4 pre[8];
        {
            const float4* src = (const float4*)hsrc;
#pragma unroll
            for (int i = 0; i < 8; ++i) pre[i] = __ldcg(src + tid + i * 128);
        }

        float acc[8] = {0.f, 0.f, 0.f, 0.f, 0.f, 0.f, 0.f, 0.f};
        for (int kc = 0; kc < 8; ++kc) {
            __syncthreads();                    // sH safe to overwrite
            {
                float4* dst = (float4*)sH;
#pragma unroll
                for (int i = 0; i < 8; ++i) dst[tid + i * 128] = pre[i];
            }
            __syncthreads();
            if (kc < 7) {
                const float4* src = (const float4*)(hsrc + (kc + 1) * 64 * 64);
#pragma unroll
                for (int i = 0; i < 8; ++i) pre[i] = __ldcg(src + tid + i * 128);
            }
#pragma unroll
            for (int k = 0; k < 64; ++k) {
                float2 hv = *(float2*)&sH[k][b0];
                float4 wv = *(float4*)&sWh[kc * 64 + k][w * 4];
                acc[0] += hv.x * wv.x; acc[1] += hv.x * wv.y;
                acc[2] += hv.x * wv.z; acc[3] += hv.x * wv.w;
                acc[4] += hv.y * wv.x; acc[5] += hv.y * wv.y;
                acc[6] += hv.y * wv.z; acc[7] += hv.y * wv.w;
            }
        }

        // gates + state update (b0 and b0+1)
        float f0 = sigf(acc[0] + xpa.x), i0 = sigf(acc[1] + xpa.y);
        float g0 = tanhf_fast(acc[2] + xpa.z), o0 = sigf(acc[3] + xpa.w);
        c0 = f0 * c0 + i0 * g0;
        float h0 = o0 * tanhf_fast(c0);

        float f1 = sigf(acc[4] + xpb.x), i1 = sigf(acc[5] + xpb.y);
        float g1 = tanhf_fast(acc[6] + xpb.z), o1 = sigf(acc[7] + xpb.w);
        c1 = f1 * c1 + i1 * g1;
        float h1 = o1 * tanhf_fast(c1);

        if (s < S_ - 1) {
            *(float2*)&g_h[wbuf * (H_ * B_) + jme * B_ + b0] = make_float2(h0, h1);
            __threadfence();
            __syncthreads();
            if (tid == 0) st_release_gpu(&g_flag[blockIdx.x * 32], s + 2);
        } else {
            d_out[B_ * O_ + (b0 + 0) * H_ + jme] = h0;
            d_out[B_ * O_ + (b0 + 1) * H_ + jme] = h1;
        }
    }
}

// ---------------- dense head ----------------
__global__ void __launch_bounds__(256) dense_out_kernel(
    const float* __restrict__ Wd, const float* __restrict__ bd,
    float* __restrict__ d_out)
{
    const int o  = blockIdx.x * 256 + threadIdx.x;
    const int b0 = blockIdx.y * 2;
    __shared__ float sh[2][H_];
    const float* hsrc = d_out + B_ * O_;
    for (int idx = threadIdx.x; idx < 2 * H_; idx += 256) {
        int bi = idx >> 9, j = idx & (H_ - 1);
        sh[bi][j] = hsrc[(b0 + bi) * H_ + j];
    }
    __syncthreads();
    if (o < O_) {
        float bias = bd[o];
        float acc0 = bias, acc1 = bias;
#pragma unroll 8
        for (int j = 0; j < H_; ++j) {
            float wv = Wd[(size_t)j * O_ + o];
            acc0 += sh[0][j] * wv;
            acc1 += sh[1][j] * wv;
        }
        d_out[(b0 + 0) * O_ + o] = acc0;
        d_out[(b0 + 1) * O_ + o] = acc1;
    }
}

// ---------------- launch ----------------
extern "C" void kernel_launch(void* const* d_in, const int* in_sizes, int n_in,
                              void* d_out, int out_size) {
    const int*   x        = (const int*)  d_in[0];
    const float* hidden   = (const float*)d_in[1];
    const float* c        = (const float*)d_in[2];
    const float* embed_w  = (const float*)d_in[3];
    const float* W_f      = (const float*)d_in[4];
    const float* b_f      = (const float*)d_in[5];
    const float* W_i      = (const float*)d_in[6];
    const float* b_i      = (const float*)d_in[7];
    const float* W_c      = (const float*)d_in[8];
    const float* b_c      = (const float*)d_in[9];
    const float* W_o      = (const float*)d_in[10];
    const float* b_o      = (const float*)d_in[11];
    const float* W_d      = (const float*)d_in[12];
    const float* b_d      = (const float*)d_in[13];
    float* out = (float*)d_out;

    static bool attr_set = false;
    if (!attr_set) {
        cudaFuncSetAttribute(xpre_mma_kernel,
                             cudaFuncAttributeMaxDynamicSharedMemorySize, XSCR + 67584);
        attr_set = true;
    }

    init_flags_kernel<<<1, NBLK>>>();
    embs_prep_kernel<<<S_, 256>>>(x, embed_w);

    dim3 gx(64, 32);
    xpre_mma_kernel<<<gx, THR, XSCR + 67584>>>(W_f, W_i, W_c, W_o, b_f, b_i, b_c, b_o);

    lstm_persistent_kernel<<<NBLK, 128>>>(hidden, c, W_f, W_i, W_c, W_o, out);

    dim3 g3(4, 32);
    dense_out_kernel<<<g3, 256>>>(W_d, b_d, out);
}